// round 7
// baseline (speedup 1.0000x reference)
#include <cuda_runtime.h>
#include <cstdint>
#include <cstddef>

// Problem constants
#define BATCH 64
#define TT 512
#define DD 1024
#define HH 1024
#define GG 4096   // 4*H
#define NBLK 128  // persistent CTAs (<=148 SMs, 1 CTA/SM)

// ---------------------------------------------------------------------------
// Packed f32x2 helpers (sm_103a FFMA2 path — 2x fp32 FMA throughput)
// ---------------------------------------------------------------------------
#define FMA2(d, a, b, c) \
    asm("fma.rn.f32x2 %0, %1, %2, %3;" : "=l"(d) : "l"(a), "l"(b), "l"(c))
#define PK2(d, lo, hi) \
    asm("mov.b64 %0, {%1, %2};" : "=l"(d) : "r"(__float_as_uint(lo)), "r"(__float_as_uint(hi)))

// ---------------------------------------------------------------------------
// Scratch (device globals: allocation-free rule)
// ---------------------------------------------------------------------------
__device__ float g_xp[(size_t)TT * BATCH * GG];     // [T][B][4H]  512 MB
__device__ float g_part[8 * BATCH * GG];            // [kslice][B][4H] 8 MB
__device__ float g_h[2][BATCH * HH];                // double-buffered h
__device__ float g_c[BATCH * HH];                   // cell state
__device__ unsigned g_bar;                          // grid barrier counter

// ---------------------------------------------------------------------------
// Init: copy h0, c0 into state buffers; reset barrier
// ---------------------------------------------------------------------------
__global__ void init_state(const float* __restrict__ h0, const float* __restrict__ c0) {
    int i = blockIdx.x * blockDim.x + threadIdx.x;
    if (i < BATCH * HH) {
        g_h[0][i] = h0[i];
        g_c[i]    = c0[i];
    }
    if (i == 0) g_bar = 0;
}

// ---------------------------------------------------------------------------
// Kernel A: xp[t][b][col] = sum_k x[b][t][k] * Wx[k][col] + bias[col]
//   M = T*B = 32768 rows (r = t*64 + b), N = 4096, K = 1024
//   BM=128, BN=128, BK=16, 256 threads, 8x8 per thread, FFMA2 inner loop
// ---------------------------------------------------------------------------
#define XBM 128
#define XBN 128
#define XBK 16

__global__ __launch_bounds__(256, 2)
void xp_gemm(const float* __restrict__ x,
             const float* __restrict__ Wfx, const float* __restrict__ Wix,
             const float* __restrict__ Wox, const float* __restrict__ Wcx,
             const float* __restrict__ bf,  const float* __restrict__ bi,
             const float* __restrict__ bo,  const float* __restrict__ bc)
{
    __shared__ float As[XBK][XBM];
    __shared__ float Bs[XBK][XBN];

    const int rowBase = blockIdx.x * XBM;
    const int colBase = blockIdx.y * XBN;
    const int gate = colBase >> 10;
    const int jBase = colBase & 1023;
    const float* __restrict__ W =
        (gate == 0) ? Wfx : (gate == 1) ? Wix : (gate == 2) ? Wox : Wcx;
    const float* __restrict__ bias =
        (gate == 0) ? bf : (gate == 1) ? bi : (gate == 2) ? bo : bc;

    const int tid = threadIdx.x;
    const int tx = tid & 15;         // col group
    const int ty = tid >> 4;         // row group

    unsigned long long acc[8][4];    // 8 rows x 4 f32x2 col-pairs
    #pragma unroll
    for (int i = 0; i < 8; i++)
        #pragma unroll
        for (int j = 0; j < 4; j++) acc[i][j] = 0ull;

    for (int k0 = 0; k0 < DD; k0 += XBK) {
        #pragma unroll
        for (int i = 0; i < 2; i++) {
            int item = tid * 2 + i;
            int r  = item >> 2;
            int k4 = item & 3;
            int rr = rowBase + r;
            int t = rr >> 6, b = rr & 63;
            const float4 a4 = *(const float4*)&x[((size_t)(b * TT + t)) * DD + k0 + k4 * 4];
            As[k4 * 4 + 0][r] = a4.x;
            As[k4 * 4 + 1][r] = a4.y;
            As[k4 * 4 + 2][r] = a4.z;
            As[k4 * 4 + 3][r] = a4.w;
        }
        #pragma unroll
        for (int i = 0; i < 2; i++) {
            int item = tid + i * 256;
            int kk = item >> 5;
            int c4 = item & 31;
            *(float4*)&Bs[kk][c4 * 4] =
                *(const float4*)&W[(size_t)(k0 + kk) * HH + jBase + c4 * 4];
        }
        __syncthreads();

        #pragma unroll
        for (int kk = 0; kk < XBK; kk++) {
            float4 a0 = *(float4*)&As[kk][ty * 8];
            float4 a1 = *(float4*)&As[kk][ty * 8 + 4];
            float4 b0 = *(float4*)&Bs[kk][tx * 8];
            float4 b1 = *(float4*)&Bs[kk][tx * 8 + 4];
            unsigned long long a2[8], b2[4];
            PK2(a2[0], a0.x, a0.x); PK2(a2[1], a0.y, a0.y);
            PK2(a2[2], a0.z, a0.z); PK2(a2[3], a0.w, a0.w);
            PK2(a2[4], a1.x, a1.x); PK2(a2[5], a1.y, a1.y);
            PK2(a2[6], a1.z, a1.z); PK2(a2[7], a1.w, a1.w);
            PK2(b2[0], b0.x, b0.y); PK2(b2[1], b0.z, b0.w);
            PK2(b2[2], b1.x, b1.y); PK2(b2[3], b1.z, b1.w);
            #pragma unroll
            for (int i = 0; i < 8; i++)
                #pragma unroll
                for (int j = 0; j < 4; j++)
                    FMA2(acc[i][j], a2[i], b2[j], acc[i][j]);
        }
        __syncthreads();
    }

    // epilogue: xp[r][col] = acc + bias
    #pragma unroll
    for (int i = 0; i < 8; i++) {
        int r = rowBase + ty * 8 + i;
        float* dst = &g_xp[(size_t)r * GG + colBase + tx * 8];
        #pragma unroll
        for (int j = 0; j < 4; j++) {
            float2 v = *(float2*)&acc[i][j];
            int jj = jBase + tx * 8 + j * 2;
            dst[j * 2 + 0] = v.x + bias[jj + 0];
            dst[j * 2 + 1] = v.y + bias[jj + 1];
        }
    }
}

// ---------------------------------------------------------------------------
// Grid barrier (all NBLK CTAs co-resident; release via fence+atomic, acquire
// via volatile spin; cross-CTA data goes through L2 with __ldcg)
// ---------------------------------------------------------------------------
__device__ __forceinline__ void grid_sync(unsigned target) {
    __syncthreads();
    if (threadIdx.x == 0) {
        __threadfence();
        atomicAdd(&g_bar, 1u);
        while (*((volatile unsigned*)&g_bar) < target) { }
    }
    __syncthreads();
}

__device__ __forceinline__ float hard_sig(float z) {
    return fminf(fmaxf(0.2f * z + 0.5f, 0.0f), 1.0f);
}

// ---------------------------------------------------------------------------
// Persistent recurrence kernel: all 512 steps in one launch.
//   CTA c -> colchunk = c & 15 (256 cols), kslice = c >> 4 (128 k)
//   Wh column-slice (128K) resident in dynamic smem for the whole kernel.
//   Per step: GEMM partials -> barrier -> elementwise (CTAs 0..63) -> barrier
// ---------------------------------------------------------------------------
__global__ __launch_bounds__(256, 1)
void lstm_persist(const float* __restrict__ Wfh, const float* __restrict__ Wih,
                  const float* __restrict__ Woh, const float* __restrict__ Wch,
                  float* __restrict__ out)
{
    extern __shared__ float sm[];
    float* Ws = sm;                 // [128][256] resident weight slice (128 KB)
    float* Hs = sm + 128 * 256;     // [16][64] staging (4 KB)

    const int cta = blockIdx.x;
    const int tid = threadIdx.x;
    const int colchunk = cta & 15;
    const int kslice   = cta >> 4;
    const int colBase = colchunk * 256;
    const int gate  = colBase >> 10;
    const int jBase = colBase & 1023;
    const float* __restrict__ W =
        (gate == 0) ? Wfh : (gate == 1) ? Wih : (gate == 2) ? Woh : Wch;
    const int kStart = kslice * 128;

    // Load resident Wh slice once: 128 k-rows x 256 cols
    for (int it = tid; it < 128 * 64; it += 256) {
        int r  = it >> 6;
        int c4 = it & 63;
        *(float4*)&Ws[r * 256 + c4 * 4] =
            *(const float4*)&W[(size_t)(kStart + r) * HH + jBase + c4 * 4];
    }
    __syncthreads();

    const int cg = tid & 31;        // 32 col groups of 8
    const int bg = tid >> 5;        // 8 batch groups of 8
    const int stage_k4 = tid >> 6;  // 0..3
    const int stage_b  = tid & 63;

    unsigned target = 0;

    for (int t = 0; t < TT; t++) {
        const int parity = t & 1;
        const float* __restrict__ h = g_h[parity];

        unsigned long long acc[8][4];
        #pragma unroll
        for (int i = 0; i < 8; i++)
            #pragma unroll
            for (int j = 0; j < 4; j++) acc[i][j] = 0ull;

        for (int ks = 0; ks < 128; ks += 16) {
            // Stage h tile: 64 b x 16 k, transposed, L2-coherent read
            {
                float4 h4 = __ldcg((const float4*)&h[stage_b * HH + kStart + ks + stage_k4 * 4]);
                Hs[(stage_k4 * 4 + 0) * 64 + stage_b] = h4.x;
                Hs[(stage_k4 * 4 + 1) * 64 + stage_b] = h4.y;
                Hs[(stage_k4 * 4 + 2) * 64 + stage_b] = h4.z;
                Hs[(stage_k4 * 4 + 3) * 64 + stage_b] = h4.w;
            }
            __syncthreads();

            #pragma unroll
            for (int kk = 0; kk < 16; kk++) {
                float4 h0 = *(float4*)&Hs[kk * 64 + bg * 8];
                float4 h1 = *(float4*)&Hs[kk * 64 + bg * 8 + 4];
                float4 w0 = *(float4*)&Ws[(ks + kk) * 256 + cg * 8];
                float4 w1 = *(float4*)&Ws[(ks + kk) * 256 + cg * 8 + 4];
                unsigned long long a2[8], b2[4];
                PK2(a2[0], h0.x, h0.x); PK2(a2[1], h0.y, h0.y);
                PK2(a2[2], h0.z, h0.z); PK2(a2[3], h0.w, h0.w);
                PK2(a2[4], h1.x, h1.x); PK2(a2[5], h1.y, h1.y);
                PK2(a2[6], h1.z, h1.z); PK2(a2[7], h1.w, h1.w);
                PK2(b2[0], w0.x, w0.y); PK2(b2[1], w0.z, w0.w);
                PK2(b2[2], w1.x, w1.y); PK2(b2[3], w1.z, w1.w);
                #pragma unroll
                for (int i = 0; i < 8; i++)
                    #pragma unroll
                    for (int j = 0; j < 4; j++)
                        FMA2(acc[i][j], a2[i], b2[j], acc[i][j]);
            }
            __syncthreads();
        }

        // Write partials (plain STG: no L1 allocate; readers use __ldcg)
        #pragma unroll
        for (int i = 0; i < 8; i++) {
            int b = bg * 8 + i;
            float* dst = &g_part[((kslice * BATCH + b) * GG) + colBase + cg * 8];
            float2 p0 = *(float2*)&acc[i][0];
            float2 p1 = *(float2*)&acc[i][1];
            float2 p2 = *(float2*)&acc[i][2];
            float2 p3 = *(float2*)&acc[i][3];
            *(float4*)&dst[0] = make_float4(p0.x, p0.y, p1.x, p1.y);
            *(float4*)&dst[4] = make_float4(p2.x, p2.y, p3.x, p3.y);
        }

        target += NBLK;
        grid_sync(target);

        // Elementwise: CTAs 0..63, each thread owns one float4 (16384 threads)
        if (cta < 64) {
            int gid = cta * 256 + tid;        // 0..16383
            int b = gid >> 8;
            int j = (gid & 255) * 4;

            const size_t xb = (size_t)(t * BATCH + b) * GG;
            float4 fz = *(const float4*)&g_xp[xb + j];
            float4 iz = *(const float4*)&g_xp[xb + 1024 + j];
            float4 oz = *(const float4*)&g_xp[xb + 2048 + j];
            float4 cz = *(const float4*)&g_xp[xb + 3072 + j];

            #pragma unroll
            for (int s = 0; s < 8; s++) {
                const float* p = &g_part[(s * BATCH + b) * GG];
                float4 pf = __ldcg((const float4*)&p[j]);
                float4 pi = __ldcg((const float4*)&p[1024 + j]);
                float4 po = __ldcg((const float4*)&p[2048 + j]);
                float4 pc = __ldcg((const float4*)&p[3072 + j]);
                fz.x += pf.x; fz.y += pf.y; fz.z += pf.z; fz.w += pf.w;
                iz.x += pi.x; iz.y += pi.y; iz.z += pi.z; iz.w += pi.w;
                oz.x += po.x; oz.y += po.y; oz.z += po.z; oz.w += po.w;
                cz.x += pc.x; cz.y += pc.y; cz.z += pc.z; cz.w += pc.w;
            }

            float4 c4 = __ldcg((const float4*)&g_c[b * HH + j]);
            float4 hn, cn;

            {
                float f = hard_sig(fz.x), i = hard_sig(iz.x), o = hard_sig(oz.x);
                float ct = tanhf(cz.x);
                cn.x = f * c4.x + i * ct;
                hn.x = o * tanhf(cn.x);
            }
            {
                float f = hard_sig(fz.y), i = hard_sig(iz.y), o = hard_sig(oz.y);
                float ct = tanhf(cz.y);
                cn.y = f * c4.y + i * ct;
                hn.y = o * tanhf(cn.y);
            }
            {
                float f = hard_sig(fz.z), i = hard_sig(iz.z), o = hard_sig(oz.z);
                float ct = tanhf(cz.z);
                cn.z = f * c4.z + i * ct;
                hn.z = o * tanhf(cn.z);
            }
            {
                float f = hard_sig(fz.w), i = hard_sig(iz.w), o = hard_sig(oz.w);
                float ct = tanhf(cz.w);
                cn.w = f * c4.w + i * ct;
                hn.w = o * tanhf(cn.w);
            }

            __stcg((float4*)&g_c[b * HH + j], cn);
            __stcg((float4*)&g_h[parity ^ 1][b * HH + j], hn);
            *(float4*)&out[((size_t)b * TT + t) * HH + j] = hn;
        }

        target += NBLK;
        grid_sync(target);
    }
}

// ---------------------------------------------------------------------------
// Launch: 3 graph nodes total (init, xp_gemm, persistent recurrence)
// ---------------------------------------------------------------------------
extern "C" void kernel_launch(void* const* d_in, const int* in_sizes, int n_in,
                              void* d_out, int out_size)
{
    const float* x   = (const float*)d_in[0];
    const float* c0  = (const float*)d_in[1];
    const float* h0  = (const float*)d_in[2];
    const float* Wfx = (const float*)d_in[3];
    const float* bf  = (const float*)d_in[4];
    const float* Wfh = (const float*)d_in[5];
    const float* Wix = (const float*)d_in[6];
    const float* bi  = (const float*)d_in[7];
    const float* Wih = (const float*)d_in[8];
    const float* Wox = (const float*)d_in[9];
    const float* bo  = (const float*)d_in[10];
    const float* Woh = (const float*)d_in[11];
    const float* Wcx = (const float*)d_in[12];
    const float* bc  = (const float*)d_in[13];
    const float* Wch = (const float*)d_in[14];
    float* out = (float*)d_out;

    const int smem_bytes = (128 * 256 + 16 * 64) * sizeof(float);  // 132 KB
    static int attr_done = 0;
    if (!attr_done) {
        cudaFuncSetAttribute(lstm_persist,
                             cudaFuncAttributeMaxDynamicSharedMemorySize, smem_bytes);
        attr_done = 1;
    }

    // init state + barrier
    init_state<<<(BATCH * HH + 255) / 256, 256>>>(h0, c0);

    // xp = x @ Wx + b  (time-major)
    dim3 xg(TT * BATCH / XBM, GG / XBN);   // (256, 32)
    xp_gemm<<<xg, 256>>>(x, Wfx, Wix, Wox, Wcx, bf, bi, bo, bc);

    // full recurrence in one persistent kernel
    lstm_persist<<<NBLK, 256, smem_bytes>>>(Wfh, Wih, Woh, Wch, out);
}

// round 11
// speedup vs baseline: 1.9870x; 1.9870x over previous
#include <cuda_runtime.h>
#include <cuda_bf16.h>
#include <cstdint>
#include <cstddef>

// Problem constants
#define BATCH 64
#define TT 512
#define DD 1024
#define HH 1024
#define GG 4096   // 4*H
#define NBLK 128  // persistent CTAs for recurrence

// ---------------------------------------------------------------------------
// mma.sync m16n8k16 bf16 (portable PTX, no arch-suffix features)
//   acc += A(16x16 row) * B(16x8 col)
// Thread mappings (PTX ISA standard):
//   A reg a0:{A[g][kc],A[g][kc+1]} a1:{A[g+8][kc],..} a2:{A[g][kc+8],..} a3:{A[g+8][kc+8],..}
//   B reg b0:{B[kc][n],B[kc+1][n]} b1:{B[kc+8][n],B[kc+9][n]}   (B stored [n][k], k-contig)
//   C reg c0:D[g][cc] c1:D[g][cc+1] c2:D[g+8][cc] c3:D[g+8][cc+1]
//   g = lane>>2, kc/cc = (lane&3)*2, n = lane>>2
// ---------------------------------------------------------------------------
__device__ __forceinline__ void mma_bf16(float* c, const uint32_t* a, const uint32_t* b) {
    asm volatile(
        "mma.sync.aligned.m16n8k16.row.col.f32.bf16.bf16.f32 "
        "{%0,%1,%2,%3}, {%4,%5,%6,%7}, {%8,%9}, {%0,%1,%2,%3};"
        : "+f"(c[0]), "+f"(c[1]), "+f"(c[2]), "+f"(c[3])
        : "r"(a[0]), "r"(a[1]), "r"(a[2]), "r"(a[3]), "r"(b[0]), "r"(b[1]));
}

// ---------------------------------------------------------------------------
// Scratch (device globals: allocation-free rule)
// g_xp is m-major: [m = b*T + t][4H]
// ---------------------------------------------------------------------------
__device__ float g_xp[(size_t)TT * BATCH * GG];     // 512 MB
__device__ float g_part[8 * BATCH * GG];            // 8 MB
__device__ float g_h[2][BATCH * HH];
__device__ float g_c[BATCH * HH];
__device__ unsigned g_bar;
__device__ float g_bias[GG];
__device__ __nv_bfloat16 g_xh[(size_t)TT * BATCH * DD];  // 64 MB  [m][k]
__device__ __nv_bfloat16 g_xl[(size_t)TT * BATCH * DD];  // 64 MB
__device__ __nv_bfloat16 g_wh[(size_t)GG * DD];          // 8 MB   [n][k]
__device__ __nv_bfloat16 g_wl[(size_t)GG * DD];          // 8 MB

// ---------------------------------------------------------------------------
// Init: h0/c0/barrier + packed bias
// ---------------------------------------------------------------------------
__global__ void init_state(const float* __restrict__ h0, const float* __restrict__ c0,
                           const float* __restrict__ bf, const float* __restrict__ bi,
                           const float* __restrict__ bo, const float* __restrict__ bc) {
    int i = blockIdx.x * blockDim.x + threadIdx.x;
    if (i < BATCH * HH) {
        g_h[0][i] = h0[i];
        g_c[i]    = c0[i];
    }
    if (i < GG) {
        int gate = i >> 10;
        const float* bsrc = (gate == 0) ? bf : (gate == 1) ? bi : (gate == 2) ? bo : bc;
        g_bias[i] = bsrc[i & 1023];
    }
    if (i == 0) g_bar = 0;
}

// ---------------------------------------------------------------------------
// conv_x: split x ([b][t][d] -> row m=b*T+t) into bf16 hi/lo
// ---------------------------------------------------------------------------
__global__ __launch_bounds__(256)
void conv_x(const float* __restrict__ x) {
    size_t i = (size_t)blockIdx.x * 256 + threadIdx.x;   // float4 index
    float4 v = ((const float4*)x)[i];
    __nv_bfloat16 h0 = __float2bfloat16(v.x);
    __nv_bfloat16 h1 = __float2bfloat16(v.y);
    __nv_bfloat16 h2 = __float2bfloat16(v.z);
    __nv_bfloat16 h3 = __float2bfloat16(v.w);
    __nv_bfloat16 l0 = __float2bfloat16(v.x - __bfloat162float(h0));
    __nv_bfloat16 l1 = __float2bfloat16(v.y - __bfloat162float(h1));
    __nv_bfloat16 l2 = __float2bfloat16(v.z - __bfloat162float(h2));
    __nv_bfloat16 l3 = __float2bfloat16(v.w - __bfloat162float(h3));
    ushort4 hv = make_ushort4(__bfloat16_as_ushort(h0), __bfloat16_as_ushort(h1),
                              __bfloat16_as_ushort(h2), __bfloat16_as_ushort(h3));
    ushort4 lv = make_ushort4(__bfloat16_as_ushort(l0), __bfloat16_as_ushort(l1),
                              __bfloat16_as_ushort(l2), __bfloat16_as_ushort(l3));
    ((ushort4*)g_xh)[i] = hv;
    ((ushort4*)g_xl)[i] = lv;
}

// ---------------------------------------------------------------------------
// conv_w: transpose W[k][n] -> wT[n][k] per gate, split into bf16 hi/lo
// ---------------------------------------------------------------------------
__global__ __launch_bounds__(256)
void conv_w(const float* __restrict__ Wf, const float* __restrict__ Wi,
            const float* __restrict__ Wo, const float* __restrict__ Wc) {
    __shared__ float tile[32][33];
    int gate = blockIdx.z;
    const float* W = (gate == 0) ? Wf : (gate == 1) ? Wi : (gate == 2) ? Wo : Wc;
    int k0 = blockIdx.x * 32;
    int n0 = blockIdx.y * 32;
    int tx = threadIdx.x, ty = threadIdx.y;   // (32, 8)
    for (int r = ty; r < 32; r += 8)
        tile[r][tx] = W[(size_t)(k0 + r) * HH + n0 + tx];
    __syncthreads();
    for (int r = ty; r < 32; r += 8) {
        float v = tile[tx][r];                 // W[k0+tx][n0+r]
        __nv_bfloat16 h = __float2bfloat16(v);
        __nv_bfloat16 l = __float2bfloat16(v - __bfloat162float(h));
        size_t o = (size_t)((gate << 10) + n0 + r) * DD + k0 + tx;
        g_wh[o] = h;
        g_wl[o] = l;
    }
}

// ---------------------------------------------------------------------------
// xp GEMM via mma.sync (split bf16): D[m][n] = sum_k x[m][k]*W[k][n] + bias
//   CTA tile 128m x 128n, K-chunk 64; 8 warps, warp tile 64m x 32n
//   grid (N/128 = 32 fastest, M/128 = 256)  -> W slices stay L2-resident
// ---------------------------------------------------------------------------
#define XPAD 72   // smem row stride in halves (64 + 8 pad -> 144B, conflict-free frags)

__global__ __launch_bounds__(256)
void xp_mma() {
    extern __shared__ __nv_bfloat16 sx[];
    __nv_bfloat16* Ah = sx;                    // [128][72]
    __nv_bfloat16* Al = Ah + 128 * XPAD;
    __nv_bfloat16* Bh = Al + 128 * XPAD;
    __nv_bfloat16* Bl = Bh + 128 * XPAD;

    const int tid  = threadIdx.x;
    const int warp = tid >> 5;
    const int lane = tid & 31;
    const int warpM = warp >> 2;               // 0..1
    const int warpN = warp & 3;                // 0..3
    const int nBase = blockIdx.x * 128;
    const int mBase = blockIdx.y * 128;

    float acc[4][4][4];
    #pragma unroll
    for (int i = 0; i < 4; i++)
        #pragma unroll
        for (int j = 0; j < 4; j++)
            #pragma unroll
            for (int q = 0; q < 4; q++) acc[i][j][q] = 0.f;

    const int g  = lane >> 2;
    const int kc = (lane & 3) * 2;

    for (int chunk = 0; chunk < 16; chunk++) {
        const int k0 = chunk * 64;
        // load A/B tiles: 128 rows x 64 halves each buffer; uint4 = 8 halves
        #pragma unroll
        for (int i = 0; i < 4; i++) {
            int item = tid + i * 256;
            int row = item >> 3, c8 = item & 7;
            size_t ga = (size_t)(mBase + row) * DD + k0 + c8 * 8;
            size_t gb = (size_t)(nBase + row) * DD + k0 + c8 * 8;
            *(uint4*)&Ah[row * XPAD + c8 * 8] = *(const uint4*)&g_xh[ga];
            *(uint4*)&Al[row * XPAD + c8 * 8] = *(const uint4*)&g_xl[ga];
            *(uint4*)&Bh[row * XPAD + c8 * 8] = *(const uint4*)&g_wh[gb];
            *(uint4*)&Bl[row * XPAD + c8 * 8] = *(const uint4*)&g_wl[gb];
        }
        __syncthreads();

        #pragma unroll
        for (int ks = 0; ks < 4; ks++) {
            const int kk = ks * 16 + kc;
            const int arow = warpM * 64 + g;
            uint32_t ah[4][4], al[4][4];
            #pragma unroll
            for (int mt = 0; mt < 4; mt++) {
                int r0 = (arow + mt * 16) * XPAD;
                int r1 = (arow + mt * 16 + 8) * XPAD;
                ah[mt][0] = *(uint32_t*)&Ah[r0 + kk];
                ah[mt][1] = *(uint32_t*)&Ah[r1 + kk];
                ah[mt][2] = *(uint32_t*)&Ah[r0 + kk + 8];
                ah[mt][3] = *(uint32_t*)&Ah[r1 + kk + 8];
                al[mt][0] = *(uint32_t*)&Al[r0 + kk];
                al[mt][1] = *(uint32_t*)&Al[r1 + kk];
                al[mt][2] = *(uint32_t*)&Al[r0 + kk + 8];
                al[mt][3] = *(uint32_t*)&Al[r1 + kk + 8];
            }
            const int brow = warpN * 32 + g;
            uint32_t bh[4][2], bl[4][2];
            #pragma unroll
            for (int nt = 0; nt < 4; nt++) {
                int rb = (brow + nt * 8) * XPAD;
                bh[nt][0] = *(uint32_t*)&Bh[rb + kk];
                bh[nt][1] = *(uint32_t*)&Bh[rb + kk + 8];
                bl[nt][0] = *(uint32_t*)&Bl[rb + kk];
                bl[nt][1] = *(uint32_t*)&Bl[rb + kk + 8];
            }
            #pragma unroll
            for (int mt = 0; mt < 4; mt++)
                #pragma unroll
                for (int nt = 0; nt < 4; nt++) {
                    mma_bf16(acc[mt][nt], ah[mt], bh[nt]);
                    mma_bf16(acc[mt][nt], ah[mt], bl[nt]);
                    mma_bf16(acc[mt][nt], al[mt], bh[nt]);
                }
        }
        __syncthreads();
    }

    // epilogue: + bias, write m-major xp
    #pragma unroll
    for (int mt = 0; mt < 4; mt++) {
        int m = mBase + warpM * 64 + mt * 16 + g;
        #pragma unroll
        for (int nt = 0; nt < 4; nt++) {
            int n = nBase + warpN * 32 + nt * 8 + kc;
            float2 bb = *(const float2*)&g_bias[n];
            float2 v0 = make_float2(acc[mt][nt][0] + bb.x, acc[mt][nt][1] + bb.y);
            float2 v1 = make_float2(acc[mt][nt][2] + bb.x, acc[mt][nt][3] + bb.y);
            *(float2*)&g_xp[(size_t)m * GG + n]       = v0;
            *(float2*)&g_xp[(size_t)(m + 8) * GG + n] = v1;
        }
    }
}
#define XP_SMEM (4 * 128 * XPAD * (int)sizeof(__nv_bfloat16))

// ---------------------------------------------------------------------------
// Grid barrier + gate math
// ---------------------------------------------------------------------------
__device__ __forceinline__ void grid_sync(unsigned target) {
    __syncthreads();
    if (threadIdx.x == 0) {
        __threadfence();
        atomicAdd(&g_bar, 1u);
        while (*((volatile unsigned*)&g_bar) < target) { }
    }
    __syncthreads();
}

__device__ __forceinline__ float hard_sig(float z) {
    return fminf(fmaxf(0.2f * z + 0.5f, 0.0f), 1.0f);
}

// ---------------------------------------------------------------------------
// Persistent recurrence: 512 steps, 128 CTAs.
//   CTA = (colchunk 0..15: 256 cols) x (kslice 0..7: 128 k)
//   Resident split Wh^T [256 n][128 k] bf16 hi/lo in smem (139 KB)
//   Per step: split h slice to bf16 hi/lo -> mma.sync partials -> barrier ->
//             elementwise (CTAs 0..63) -> barrier
// ---------------------------------------------------------------------------
#define RPAD 136  // 128 + 8 pad halves -> 272B stride, conflict-free frags

__global__ __launch_bounds__(256, 1)
void lstm_persist(const float* __restrict__ Wfh, const float* __restrict__ Wih,
                  const float* __restrict__ Woh, const float* __restrict__ Wch,
                  float* __restrict__ out)
{
    extern __shared__ __nv_bfloat16 sm[];
    __nv_bfloat16* Wsh = sm;                    // [256][136]
    __nv_bfloat16* Wsl = Wsh + 256 * RPAD;
    __nv_bfloat16* Hh  = Wsl + 256 * RPAD;      // [64][136]
    __nv_bfloat16* Hl  = Hh + 64 * RPAD;

    const int cta = blockIdx.x;
    const int tid = threadIdx.x;
    const int colchunk = cta & 15;
    const int kslice   = cta >> 4;
    const int colBase = colchunk * 256;
    const int gate  = colBase >> 10;
    const int jBase = colBase & 1023;
    const float* __restrict__ W =
        (gate == 0) ? Wfh : (gate == 1) ? Wih : (gate == 2) ? Woh : Wch;
    const int kStart = kslice * 128;

    // Resident split weights: transpose + split W[k][n] -> [n][k] hi/lo
    for (int it = tid; it < 128 * 256; it += 256) {
        int k = it >> 8, n = it & 255;           // coalesced over n
        float v = W[(size_t)(kStart + k) * HH + jBase + n];
        __nv_bfloat16 hi = __float2bfloat16(v);
        Wsh[n * RPAD + k] = hi;
        Wsl[n * RPAD + k] = __float2bfloat16(v - __bfloat162float(hi));
    }
    __syncthreads();

    const int warp = tid >> 5;    // warpN: 8 warps x 32 cols = 256 cols
    const int lane = tid & 31;
    const int g  = lane >> 2;
    const int kc = (lane & 3) * 2;

    unsigned target = 0;

    for (int t = 0; t < TT; t++) {
        const int parity = t & 1;
        const float* __restrict__ h = g_h[parity];

        // stage h slice: split fp32 -> bf16 hi/lo  (64 b x 128 k)
        for (int it = tid; it < 64 * 128; it += 256) {
            int b = it >> 7, k = it & 127;
            float v = __ldcg(&h[b * HH + kStart + k]);
            __nv_bfloat16 hi = __float2bfloat16(v);
            Hh[b * RPAD + k] = hi;
            Hl[b * RPAD + k] = __float2bfloat16(v - __bfloat162float(hi));
        }
        __syncthreads();

        float acc[4][4][4];
        #pragma unroll
        for (int i = 0; i < 4; i++)
            #pragma unroll
            for (int j = 0; j < 4; j++)
                #pragma unroll
                for (int q = 0; q < 4; q++) acc[i][j][q] = 0.f;

        #pragma unroll
        for (int ks = 0; ks < 8; ks++) {
            const int kk = ks * 16 + kc;
            uint32_t ah[4][4], al[4][4];
            #pragma unroll
            for (int mt = 0; mt < 4; mt++) {
                int r0 = (mt * 16 + g) * RPAD;
                int r1 = (mt * 16 + 8 + g) * RPAD;
                ah[mt][0] = *(uint32_t*)&Hh[r0 + kk];
                ah[mt][1] = *(uint32_t*)&Hh[r1 + kk];
                ah[mt][2] = *(uint32_t*)&Hh[r0 + kk + 8];
                ah[mt][3] = *(uint32_t*)&Hh[r1 + kk + 8];
                al[mt][0] = *(uint32_t*)&Hl[r0 + kk];
                al[mt][1] = *(uint32_t*)&Hl[r1 + kk];
                al[mt][2] = *(uint32_t*)&Hl[r0 + kk + 8];
                al[mt][3] = *(uint32_t*)&Hl[r1 + kk + 8];
            }
            const int brow = warp * 32 + g;
            uint32_t bh[4][2], bl[4][2];
            #pragma unroll
            for (int nt = 0; nt < 4; nt++) {
                int rb = (brow + nt * 8) * RPAD;
                bh[nt][0] = *(uint32_t*)&Wsh[rb + kk];
                bh[nt][1] = *(uint32_t*)&Wsh[rb + kk + 8];
                bl[nt][0] = *(uint32_t*)&Wsl[rb + kk];
                bl[nt][1] = *(uint32_t*)&Wsl[rb + kk + 8];
            }
            #pragma unroll
            for (int mt = 0; mt < 4; mt++)
                #pragma unroll
                for (int nt = 0; nt < 4; nt++) {
                    mma_bf16(acc[mt][nt], ah[mt], bh[nt]);
                    mma_bf16(acc[mt][nt], ah[mt], bl[nt]);
                    mma_bf16(acc[mt][nt], al[mt], bh[nt]);
                }
        }

        // write partials (plain STG; readers use __ldcg)
        #pragma unroll
        for (int mt = 0; mt < 4; mt++) {
            int b0 = mt * 16 + g;
            #pragma unroll
            for (int nt = 0; nt < 4; nt++) {
                int n = colBase + warp * 32 + nt * 8 + kc;
                *(float2*)&g_part[(size_t)(kslice * BATCH + b0) * GG + n] =
                    make_float2(acc[mt][nt][0], acc[mt][nt][1]);
                *(float2*)&g_part[(size_t)(kslice * BATCH + b0 + 8) * GG + n] =
                    make_float2(acc[mt][nt][2], acc[mt][nt][3]);
            }
        }

        target += NBLK;
        grid_sync(target);

        // Elementwise: CTAs 0..63, one float4 per thread
        if (cta < 64) {
            int gid = cta * 256 + tid;
            int b = gid >> 8;
            int j = (gid & 255) * 4;

            const size_t xb = (size_t)(b * TT + t) * GG;   // m-major xp
            float4 fz = *(const float4*)&g_xp[xb + j];
            float4 iz = *(const float4*)&g_xp[xb + 1024 + j];
            float4 oz = *(const float4*)&g_xp[xb + 2048 + j];
            float4 cz = *(const float4*)&g_xp[xb + 3072 + j];

            #pragma unroll
            for (int s = 0; s < 8; s++) {
                const float* p = &g_part[(size_t)(s * BATCH + b) * GG];
                float4 pf = __ldcg((const float4*)&p[j]);
                float4 pi = __ldcg((const float4*)&p[1024 + j]);
                float4 po = __ldcg((const float4*)&p[2048 + j]);
                float4 pc = __ldcg((const float4*)&p[3072 + j]);
                fz.x += pf.x; fz.y += pf.y; fz.z += pf.z; fz.w += pf.w;
                iz.x += pi.x; iz.y += pi.y; iz.z += pi.z; iz.w += pi.w;
                oz.x += po.x; oz.y += po.y; oz.z += po.z; oz.w += po.w;
                cz.x += pc.x; cz.y += pc.y; cz.z += pc.z; cz.w += pc.w;
            }

            float4 c4 = __ldcg((const float4*)&g_c[b * HH + j]);
            float4 hn, cn;
            {
                float f = hard_sig(fz.x), i = hard_sig(iz.x), o = hard_sig(oz.x);
                float ct = tanhf(cz.x);
                cn.x = f * c4.x + i * ct; hn.x = o * tanhf(cn.x);
            }
            {
                float f = hard_sig(fz.y), i = hard_sig(iz.y), o = hard_sig(oz.y);
                float ct = tanhf(cz.y);
                cn.y = f * c4.y + i * ct; hn.y = o * tanhf(cn.y);
            }
            {
                float f = hard_sig(fz.z), i = hard_sig(iz.z), o = hard_sig(oz.z);
                float ct = tanhf(cz.z);
                cn.z = f * c4.z + i * ct; hn.z = o * tanhf(cn.z);
            }
            {
                float f = hard_sig(fz.w), i = hard_sig(iz.w), o = hard_sig(oz.w);
                float ct = tanhf(cz.w);
                cn.w = f * c4.w + i * ct; hn.w = o * tanhf(cn.w);
            }

            __stcg((float4*)&g_c[b * HH + j], cn);
            __stcg((float4*)&g_h[parity ^ 1][b * HH + j], hn);
            *(float4*)&out[((size_t)b * TT + t) * HH + j] = hn;
        }

        target += NBLK;
        grid_sync(target);
    }
}
#define REC_SMEM ((2 * 256 * RPAD + 2 * 64 * RPAD) * (int)sizeof(__nv_bfloat16))

// ---------------------------------------------------------------------------
// Launch: 5 graph nodes (init, conv_x, conv_w, xp_mma, lstm_persist)
// ---------------------------------------------------------------------------
extern "C" void kernel_launch(void* const* d_in, const int* in_sizes, int n_in,
                              void* d_out, int out_size)
{
    const float* x   = (const float*)d_in[0];
    const float* c0  = (const float*)d_in[1];
    const float* h0  = (const float*)d_in[2];
    const float* Wfx = (const float*)d_in[3];
    const float* bf  = (const float*)d_in[4];
    const float* Wfh = (const float*)d_in[5];
    const float* Wix = (const float*)d_in[6];
    const float* bi  = (const float*)d_in[7];
    const float* Wih = (const float*)d_in[8];
    const float* Wox = (const float*)d_in[9];
    const float* bo  = (const float*)d_in[10];
    const float* Woh = (const float*)d_in[11];
    const float* Wcx = (const float*)d_in[12];
    const float* bc  = (const float*)d_in[13];
    const float* Wch = (const float*)d_in[14];
    float* out = (float*)d_out;

    cudaFuncSetAttribute(lstm_persist, cudaFuncAttributeMaxDynamicSharedMemorySize, REC_SMEM);
    cudaFuncSetAttribute(xp_mma, cudaFuncAttributeMaxDynamicSharedMemorySize, XP_SMEM);

    init_state<<<(BATCH * HH + 255) / 256, 256>>>(h0, c0, bf, bi, bo, bc);

    // bf16 split conversions
    conv_x<<<(int)(((size_t)TT * BATCH * DD / 4) / 256), 256>>>(x);
    dim3 wg(DD / 32, HH / 32, 4);
    conv_w<<<wg, dim3(32, 8)>>>(Wfx, Wix, Wox, Wcx);

    // xp = x @ Wx + b via mma.sync (n-blocks fastest -> W L2-resident)
    dim3 xg(GG / 128, TT * BATCH / 128);   // (32, 256)
    xp_mma<<<xg, 256, XP_SMEM>>>();

    // recurrence (persistent, mma.sync split-bf16)
    lstm_persist<<<NBLK, 256, REC_SMEM>>>(Wfh, Wih, Woh, Wch, out);
}

// round 14
// speedup vs baseline: 2.3112x; 1.1632x over previous
#include <cuda_runtime.h>
#include <cuda_bf16.h>
#include <cstdint>
#include <cstddef>

// Problem constants
#define BATCH 64
#define TT 512
#define DD 1024
#define HH 1024
#define GG 4096   // 4*H
#define NBLK 128  // persistent CTAs for recurrence

// ---------------------------------------------------------------------------
// mma.sync m16n8k16 bf16 (portable PTX)
// ---------------------------------------------------------------------------
__device__ __forceinline__ void mma_bf16(float* c, const uint32_t* a, const uint32_t* b) {
    asm volatile(
        "mma.sync.aligned.m16n8k16.row.col.f32.bf16.bf16.f32 "
        "{%0,%1,%2,%3}, {%4,%5,%6,%7}, {%8,%9}, {%0,%1,%2,%3};"
        : "+f"(c[0]), "+f"(c[1]), "+f"(c[2]), "+f"(c[3])
        : "r"(a[0]), "r"(a[1]), "r"(a[2]), "r"(a[3]), "r"(b[0]), "r"(b[1]));
}

// cp.async helpers (sm_80 baseline PTX) — used ONLY for prior-kernel data (xp)
__device__ __forceinline__ uint32_t s2u(const void* p) {
    return (uint32_t)__cvta_generic_to_shared(p);
}
#define CP_ASYNC16(dst_u32, src_ptr) \
    asm volatile("cp.async.cg.shared.global [%0], [%1], 16;" :: "r"(dst_u32), "l"(src_ptr))
#define CP_COMMIT() asm volatile("cp.async.commit_group;")
#define CP_WAIT0() asm volatile("cp.async.wait_group 0;")
#define CP_WAIT1() asm volatile("cp.async.wait_group 1;")

// ---------------------------------------------------------------------------
// Scratch (device globals)
// ---------------------------------------------------------------------------
__device__ float g_xp[(size_t)TT * BATCH * GG];     // [m=b*T+t][4H] 512 MB
__device__ float g_part[4 * BATCH * GG];            // [kslice][B][4H] 4 MB
__device__ float g_c[BATCH * HH];
__device__ float g_bias[GG];
__device__ unsigned g_flags[NBLK * 32];             // barrier flags, 128B stride
__device__ __nv_bfloat16 g_xh[(size_t)TT * BATCH * DD];  // [m][k]
__device__ __nv_bfloat16 g_xl[(size_t)TT * BATCH * DD];
__device__ __nv_bfloat16 g_wh[(size_t)GG * DD];          // [n][k]
__device__ __nv_bfloat16 g_wl[(size_t)GG * DD];
__device__ __nv_bfloat16 g_hh[BATCH * HH];               // split h state
__device__ __nv_bfloat16 g_hl[BATCH * HH];

// ---------------------------------------------------------------------------
// Init: c0, split h0, packed bias, barrier flags
// ---------------------------------------------------------------------------
__global__ void init_state(const float* __restrict__ h0, const float* __restrict__ c0,
                           const float* __restrict__ bf, const float* __restrict__ bi,
                           const float* __restrict__ bo, const float* __restrict__ bc) {
    int i = blockIdx.x * blockDim.x + threadIdx.x;
    if (i < BATCH * HH) {
        float v = h0[i];
        __nv_bfloat16 hi = __float2bfloat16(v);
        g_hh[i] = hi;
        g_hl[i] = __float2bfloat16(v - __bfloat162float(hi));
        g_c[i]  = c0[i];
    }
    if (i < GG) {
        int gate = i >> 10;
        const float* bsrc = (gate == 0) ? bf : (gate == 1) ? bi : (gate == 2) ? bo : bc;
        g_bias[i] = bsrc[i & 1023];
    }
    if (i < NBLK * 32) g_flags[i] = 0u;
}

// ---------------------------------------------------------------------------
// conv_x: split x into bf16 hi/lo
// ---------------------------------------------------------------------------
__global__ __launch_bounds__(256)
void conv_x(const float* __restrict__ x) {
    size_t i = (size_t)blockIdx.x * 256 + threadIdx.x;   // float4 index
    float4 v = ((const float4*)x)[i];
    __nv_bfloat16 h0 = __float2bfloat16(v.x);
    __nv_bfloat16 h1 = __float2bfloat16(v.y);
    __nv_bfloat16 h2 = __float2bfloat16(v.z);
    __nv_bfloat16 h3 = __float2bfloat16(v.w);
    __nv_bfloat16 l0 = __float2bfloat16(v.x - __bfloat162float(h0));
    __nv_bfloat16 l1 = __float2bfloat16(v.y - __bfloat162float(h1));
    __nv_bfloat16 l2 = __float2bfloat16(v.z - __bfloat162float(h2));
    __nv_bfloat16 l3 = __float2bfloat16(v.w - __bfloat162float(h3));
    ((ushort4*)g_xh)[i] = make_ushort4(__bfloat16_as_ushort(h0), __bfloat16_as_ushort(h1),
                                       __bfloat16_as_ushort(h2), __bfloat16_as_ushort(h3));
    ((ushort4*)g_xl)[i] = make_ushort4(__bfloat16_as_ushort(l0), __bfloat16_as_ushort(l1),
                                       __bfloat16_as_ushort(l2), __bfloat16_as_ushort(l3));
}

// ---------------------------------------------------------------------------
// conv_w: transpose W[k][n] -> [n][k] per gate, split bf16 hi/lo
// ---------------------------------------------------------------------------
__global__ __launch_bounds__(256)
void conv_w(const float* __restrict__ Wf, const float* __restrict__ Wi,
            const float* __restrict__ Wo, const float* __restrict__ Wc) {
    __shared__ float tile[32][33];
    int gate = blockIdx.z;
    const float* W = (gate == 0) ? Wf : (gate == 1) ? Wi : (gate == 2) ? Wo : Wc;
    int k0 = blockIdx.x * 32;
    int n0 = blockIdx.y * 32;
    int tx = threadIdx.x, ty = threadIdx.y;   // (32, 8)
    for (int r = ty; r < 32; r += 8)
        tile[r][tx] = W[(size_t)(k0 + r) * HH + n0 + tx];
    __syncthreads();
    for (int r = ty; r < 32; r += 8) {
        float v = tile[tx][r];
        __nv_bfloat16 h = __float2bfloat16(v);
        size_t o = (size_t)((gate << 10) + n0 + r) * DD + k0 + tx;
        g_wh[o] = h;
        g_wl[o] = __float2bfloat16(v - __bfloat162float(h));
    }
}

// ---------------------------------------------------------------------------
// xp GEMM: 128m x 128n tiles, K-chunk 64, 2-stage cp.async pipeline
// (cp.async here reads only data produced by PRIOR kernels — no intra-kernel
//  producer/consumer through the async path)
// ---------------------------------------------------------------------------
#define XPAD 72
#define XSZ (128 * XPAD)

__global__ __launch_bounds__(256)
void xp_mma() {
    extern __shared__ __nv_bfloat16 sx[];   // [2 stages][4 bufs][128*72]

    const int tid  = threadIdx.x;
    const int warp = tid >> 5;
    const int lane = tid & 31;
    const int warpM = warp >> 2;
    const int warpN = warp & 3;
    const int nBase = blockIdx.x * 128;
    const int mBase = blockIdx.y * 128;

    float acc[4][4][4];
    #pragma unroll
    for (int i = 0; i < 4; i++)
        #pragma unroll
        for (int j = 0; j < 4; j++)
            #pragma unroll
            for (int q = 0; q < 4; q++) acc[i][j][q] = 0.f;

    const int g  = lane >> 2;
    const int kc = (lane & 3) * 2;

    auto prefetch = [&](int chunk, int stage) {
        __nv_bfloat16* Ah = sx + (stage * 4 + 0) * XSZ;
        __nv_bfloat16* Al = sx + (stage * 4 + 1) * XSZ;
        __nv_bfloat16* Bh = sx + (stage * 4 + 2) * XSZ;
        __nv_bfloat16* Bl = sx + (stage * 4 + 3) * XSZ;
        const int k0 = chunk * 64;
        #pragma unroll
        for (int i = 0; i < 4; i++) {
            int item = tid + i * 256;
            int row = item >> 3, c8 = item & 7;
            size_t ga = (size_t)(mBase + row) * DD + k0 + c8 * 8;
            size_t gb = (size_t)(nBase + row) * DD + k0 + c8 * 8;
            uint32_t so = (row * XPAD + c8 * 8) * 2;
            CP_ASYNC16(s2u(Ah) + so, &g_xh[ga]);
            CP_ASYNC16(s2u(Al) + so, &g_xl[ga]);
            CP_ASYNC16(s2u(Bh) + so, &g_wh[gb]);
            CP_ASYNC16(s2u(Bl) + so, &g_wl[gb]);
        }
        CP_COMMIT();
    };

    prefetch(0, 0);

    for (int chunk = 0; chunk < 16; chunk++) {
        const int cur = chunk & 1;
        if (chunk < 15) prefetch(chunk + 1, cur ^ 1);
        if (chunk < 15) { CP_WAIT1(); } else { CP_WAIT0(); }
        __syncthreads();

        __nv_bfloat16* Ah = sx + (cur * 4 + 0) * XSZ;
        __nv_bfloat16* Al = sx + (cur * 4 + 1) * XSZ;
        __nv_bfloat16* Bh = sx + (cur * 4 + 2) * XSZ;
        __nv_bfloat16* Bl = sx + (cur * 4 + 3) * XSZ;

        #pragma unroll
        for (int ks = 0; ks < 4; ks++) {
            const int kk = ks * 16 + kc;
            const int arow = warpM * 64 + g;
            uint32_t ah[4][4], al[4][4];
            #pragma unroll
            for (int mt = 0; mt < 4; mt++) {
                int r0 = (arow + mt * 16) * XPAD;
                int r1 = (arow + mt * 16 + 8) * XPAD;
                ah[mt][0] = *(uint32_t*)&Ah[r0 + kk];
                ah[mt][1] = *(uint32_t*)&Ah[r1 + kk];
                ah[mt][2] = *(uint32_t*)&Ah[r0 + kk + 8];
                ah[mt][3] = *(uint32_t*)&Ah[r1 + kk + 8];
                al[mt][0] = *(uint32_t*)&Al[r0 + kk];
                al[mt][1] = *(uint32_t*)&Al[r1 + kk];
                al[mt][2] = *(uint32_t*)&Al[r0 + kk + 8];
                al[mt][3] = *(uint32_t*)&Al[r1 + kk + 8];
            }
            const int brow = warpN * 32 + g;
            uint32_t bh[4][2], bl[4][2];
            #pragma unroll
            for (int nt = 0; nt < 4; nt++) {
                int rb = (brow + nt * 8) * XPAD;
                bh[nt][0] = *(uint32_t*)&Bh[rb + kk];
                bh[nt][1] = *(uint32_t*)&Bh[rb + kk + 8];
                bl[nt][0] = *(uint32_t*)&Bl[rb + kk];
                bl[nt][1] = *(uint32_t*)&Bl[rb + kk + 8];
            }
            #pragma unroll
            for (int mt = 0; mt < 4; mt++)
                #pragma unroll
                for (int nt = 0; nt < 4; nt++) {
                    mma_bf16(acc[mt][nt], ah[mt], bh[nt]);
                    mma_bf16(acc[mt][nt], ah[mt], bl[nt]);
                    mma_bf16(acc[mt][nt], al[mt], bh[nt]);
                }
        }
        __syncthreads();
    }

    #pragma unroll
    for (int mt = 0; mt < 4; mt++) {
        int m = mBase + warpM * 64 + mt * 16 + g;
        #pragma unroll
        for (int nt = 0; nt < 4; nt++) {
            int n = nBase + warpN * 32 + nt * 8 + kc;
            float2 bb = *(const float2*)&g_bias[n];
            *(float2*)&g_xp[(size_t)m * GG + n] =
                make_float2(acc[mt][nt][0] + bb.x, acc[mt][nt][1] + bb.y);
            *(float2*)&g_xp[(size_t)(m + 8) * GG + n] =
                make_float2(acc[mt][nt][2] + bb.x, acc[mt][nt][3] + bb.y);
        }
    }
}
#define XP_SMEM (2 * 4 * XSZ * (int)sizeof(__nv_bfloat16))   // 147456

// ---------------------------------------------------------------------------
// Grid barrier with FORMAL release/acquire semantics (PTX memory model):
//   producer: all CTA stores -> __syncthreads -> st.release.gpu flag
//   consumer: ld.acquire.gpu spin -> __syncthreads -> reads
// ---------------------------------------------------------------------------
__device__ __forceinline__ void barrier_sync(int cta, unsigned seq) {
    __syncthreads();
    if (threadIdx.x == 0)
        asm volatile("st.release.gpu.global.u32 [%0], %1;"
                     :: "l"(&g_flags[cta * 32]), "r"(seq) : "memory");
    if (threadIdx.x < NBLK) {
        const unsigned* p = &g_flags[threadIdx.x * 32];
        unsigned v;
        do {
            asm volatile("ld.acquire.gpu.global.u32 %0, [%1];"
                         : "=r"(v) : "l"(p) : "memory");
        } while (v < seq);
    }
    __syncthreads();
}

__device__ __forceinline__ float hard_sig(float z) {
    return fminf(fmaxf(0.2f * z + 0.5f, 0.0f), 1.0f);
}

// ---------------------------------------------------------------------------
// Persistent recurrence: 512 steps, 128 CTAs = 32 colchunks(128n) x 4 kslices(256k)
//   Resident split Wh^T [128n][256k] hi/lo (135 KB); h staged from global bf16
//   via __ldcg+STS (L2-coherent). Elementwise over all 128 CTAs writes split
//   bf16 h via __stcg. All cross-CTA traffic is .cg (L2), ordered by the
//   release/acquire barrier.
// ---------------------------------------------------------------------------
#define RPAD 264   // 256 + 8 halves -> 528B row stride

__global__ __launch_bounds__(256, 1)
void lstm_persist(const float* __restrict__ Wfh, const float* __restrict__ Wih,
                  const float* __restrict__ Woh, const float* __restrict__ Wch,
                  float* __restrict__ out)
{
    extern __shared__ __nv_bfloat16 sm[];
    __nv_bfloat16* Wsh = sm;                    // [128][264]
    __nv_bfloat16* Wsl = Wsh + 128 * RPAD;
    __nv_bfloat16* Hh  = Wsl + 128 * RPAD;      // [64][264]
    __nv_bfloat16* Hl  = Hh + 64 * RPAD;

    const int cta = blockIdx.x;
    const int tid = threadIdx.x;
    const int colchunk = cta & 31;              // 32 chunks of 128 cols
    const int kslice   = cta >> 5;              // 4 slices of 256 k
    const int colBase = colchunk * 128;
    const int gate  = colBase >> 10;
    const int jBase = colBase & 1023;
    const float* __restrict__ W =
        (gate == 0) ? Wfh : (gate == 1) ? Wih : (gate == 2) ? Woh : Wch;
    const int kStart = kslice * 256;

    // Resident split weights: transpose W[k][n] -> [n][k] hi/lo (one-time)
    for (int it = tid; it < 256 * 128; it += 256) {
        int k = it >> 7, n = it & 127;          // coalesced over n
        float v = W[(size_t)(kStart + k) * HH + jBase + n];
        __nv_bfloat16 hi = __float2bfloat16(v);
        Wsh[n * RPAD + k] = hi;
        Wsl[n * RPAD + k] = __float2bfloat16(v - __bfloat162float(hi));
    }
    __syncthreads();

    const int warp = tid >> 5;
    const int lane = tid & 31;
    const int warpM = warp & 1;                 // 2 x 32 rows
    const int warpN = warp >> 1;                // 4 x 32 cols
    const int g  = lane >> 2;
    const int kc = (lane & 3) * 2;

    unsigned seq = 0;

    for (int t = 0; t < TT; t++) {
        // stage split h slice [64][256]: __ldcg (L2) -> STS
        #pragma unroll
        for (int i = 0; i < 8; i++) {
            int item = tid + i * 256;           // 2048 16B-chunks per buffer
            int row = item >> 5, c8 = item & 31;
            size_t gsrc = (size_t)row * HH + kStart + c8 * 8;
            uint4 vh = __ldcg((const uint4*)&g_hh[gsrc]);
            uint4 vl = __ldcg((const uint4*)&g_hl[gsrc]);
            *(uint4*)&Hh[row * RPAD + c8 * 8] = vh;
            *(uint4*)&Hl[row * RPAD + c8 * 8] = vl;
        }
        __syncthreads();

        float acc[2][4][4];
        #pragma unroll
        for (int i = 0; i < 2; i++)
            #pragma unroll
            for (int j = 0; j < 4; j++)
                #pragma unroll
                for (int q = 0; q < 4; q++) acc[i][j][q] = 0.f;

        #pragma unroll
        for (int ks = 0; ks < 16; ks++) {
            const int kk = ks * 16 + kc;
            uint32_t ah[2][4], al[2][4];
            #pragma unroll
            for (int mt = 0; mt < 2; mt++) {
                int r0 = (warpM * 32 + mt * 16 + g) * RPAD;
                int r1 = r0 + 8 * RPAD;
                ah[mt][0] = *(uint32_t*)&Hh[r0 + kk];
                ah[mt][1] = *(uint32_t*)&Hh[r1 + kk];
                ah[mt][2] = *(uint32_t*)&Hh[r0 + kk + 8];
                ah[mt][3] = *(uint32_t*)&Hh[r1 + kk + 8];
                al[mt][0] = *(uint32_t*)&Hl[r0 + kk];
                al[mt][1] = *(uint32_t*)&Hl[r1 + kk];
                al[mt][2] = *(uint32_t*)&Hl[r0 + kk + 8];
                al[mt][3] = *(uint32_t*)&Hl[r1 + kk + 8];
            }
            uint32_t bh[4][2], bl[4][2];
            #pragma unroll
            for (int nt = 0; nt < 4; nt++) {
                int rb = (warpN * 32 + nt * 8 + g) * RPAD;
                bh[nt][0] = *(uint32_t*)&Wsh[rb + kk];
                bh[nt][1] = *(uint32_t*)&Wsh[rb + kk + 8];
                bl[nt][0] = *(uint32_t*)&Wsl[rb + kk];
                bl[nt][1] = *(uint32_t*)&Wsl[rb + kk + 8];
            }
            #pragma unroll
            for (int mt = 0; mt < 2; mt++)
                #pragma unroll
                for (int nt = 0; nt < 4; nt++) {
                    mma_bf16(acc[mt][nt], ah[mt], bh[nt]);
                    mma_bf16(acc[mt][nt], ah[mt], bl[nt]);
                    mma_bf16(acc[mt][nt], al[mt], bh[nt]);
                }
        }

        // write partials to L2 (__stcg)
        #pragma unroll
        for (int mt = 0; mt < 2; mt++) {
            int b0 = warpM * 32 + mt * 16 + g;
            #pragma unroll
            for (int nt = 0; nt < 4; nt++) {
                int n = colBase + warpN * 32 + nt * 8 + kc;
                __stcg((float2*)&g_part[(size_t)(kslice * BATCH + b0) * GG + n],
                       make_float2(acc[mt][nt][0], acc[mt][nt][1]));
                __stcg((float2*)&g_part[(size_t)(kslice * BATCH + b0 + 8) * GG + n],
                       make_float2(acc[mt][nt][2], acc[mt][nt][3]));
            }
        }

        barrier_sync(cta, ++seq);

        // elementwise: all 128 CTAs, 2 h-elements per thread (64K total)
        {
            int e = cta * 512 + tid * 2;
            int b = e >> 10;
            int j = e & 1023;

            const size_t xb = (size_t)(b * TT + t) * GG;
            float2 fz = *(const float2*)&g_xp[xb + j];
            float2 iz = *(const float2*)&g_xp[xb + 1024 + j];
            float2 oz = *(const float2*)&g_xp[xb + 2048 + j];
            float2 cz = *(const float2*)&g_xp[xb + 3072 + j];

            #pragma unroll
            for (int s = 0; s < 4; s++) {
                const float* p = &g_part[(size_t)(s * BATCH + b) * GG];
                float2 pf = __ldcg((const float2*)&p[j]);
                float2 pi = __ldcg((const float2*)&p[1024 + j]);
                float2 po = __ldcg((const float2*)&p[2048 + j]);
                float2 pc = __ldcg((const float2*)&p[3072 + j]);
                fz.x += pf.x; fz.y += pf.y;
                iz.x += pi.x; iz.y += pi.y;
                oz.x += po.x; oz.y += po.y;
                cz.x += pc.x; cz.y += pc.y;
            }

            float2 cc = __ldcg((const float2*)&g_c[b * HH + j]);
            float2 hn, cn;
            {
                float f = hard_sig(fz.x), i = hard_sig(iz.x), o = hard_sig(oz.x);
                float ct = tanhf(cz.x);
                cn.x = f * cc.x + i * ct; hn.x = o * tanhf(cn.x);
            }
            {
                float f = hard_sig(fz.y), i = hard_sig(iz.y), o = hard_sig(oz.y);
                float ct = tanhf(cz.y);
                cn.y = f * cc.y + i * ct; hn.y = o * tanhf(cn.y);
            }

            __stcg((float2*)&g_c[b * HH + j], cn);

            // split h -> bf16 hi/lo, packed 2-wide L2 stores
            __nv_bfloat16 hx = __float2bfloat16(hn.x);
            __nv_bfloat16 hy = __float2bfloat16(hn.y);
            __nv_bfloat16 lx = __float2bfloat16(hn.x - __bfloat162float(hx));
            __nv_bfloat16 ly = __float2bfloat16(hn.y - __bfloat162float(hy));
            uint32_t ph = (uint32_t)__bfloat16_as_ushort(hx) |
                          ((uint32_t)__bfloat16_as_ushort(hy) << 16);
            uint32_t pl = (uint32_t)__bfloat16_as_ushort(lx) |
                          ((uint32_t)__bfloat16_as_ushort(ly) << 16);
            __stcg((unsigned int*)&g_hh[b * HH + j], ph);
            __stcg((unsigned int*)&g_hl[b * HH + j], pl);

            *(float2*)&out[((size_t)b * TT + t) * HH + j] = hn;
        }

        barrier_sync(cta, ++seq);
    }
}
#define REC_SMEM ((2 * 128 * RPAD + 2 * 64 * RPAD) * (int)sizeof(__nv_bfloat16))  // 202752

// ---------------------------------------------------------------------------
// Launch: 5 graph nodes
// ---------------------------------------------------------------------------
extern "C" void kernel_launch(void* const* d_in, const int* in_sizes, int n_in,
                              void* d_out, int out_size)
{
    const float* x   = (const float*)d_in[0];
    const float* c0  = (const float*)d_in[1];
    const float* h0  = (const float*)d_in[2];
    const float* Wfx = (const float*)d_in[3];
    const float* bf  = (const float*)d_in[4];
    const float* Wfh = (const float*)d_in[5];
    const float* Wix = (const float*)d_in[6];
    const float* bi  = (const float*)d_in[7];
    const float* Wih = (const float*)d_in[8];
    const float* Wox = (const float*)d_in[9];
    const float* bo  = (const float*)d_in[10];
    const float* Woh = (const float*)d_in[11];
    const float* Wcx = (const float*)d_in[12];
    const float* bc  = (const float*)d_in[13];
    const float* Wch = (const float*)d_in[14];
    float* out = (float*)d_out;

    cudaFuncSetAttribute(lstm_persist, cudaFuncAttributeMaxDynamicSharedMemorySize, REC_SMEM);
    cudaFuncSetAttribute(xp_mma, cudaFuncAttributeMaxDynamicSharedMemorySize, XP_SMEM);

    init_state<<<(BATCH * HH + 255) / 256, 256>>>(h0, c0, bf, bi, bo, bc);

    conv_x<<<(int)(((size_t)TT * BATCH * DD / 4) / 256), 256>>>(x);
    dim3 wg(DD / 32, HH / 32, 4);
    conv_w<<<wg, dim3(32, 8)>>>(Wfx, Wix, Wox, Wcx);

    dim3 xg(GG / 128, TT * BATCH / 128);   // (32, 256), n fastest
    xp_mma<<<xg, 256, XP_SMEM>>>();

    lstm_persist<<<NBLK, 256, REC_SMEM>>>(Wfh, Wih, Woh, Wch, out);
}